// round 17
// baseline (speedup 1.0000x reference)
#include <cuda_runtime.h>
#include <math.h>

// Problem constants (N=128 images, P=16 control points, S=128 grid)
#define NIMG 128
#define NP   16
#define NSEG (NP-1)            // 15 segments
#define SDIM 128
#define RAD  4                 // 9-tap Gaussian: dropped taps <= 1.1e-7 (safe vs 1e-3 tol)
#define KW   (2*RAD+1)

#define BT     256             // threads per CTA
#define SLICES 8               // CTAs per image
#define SR     16              // output rows per CTA
#define LR     (SR + 2*RAD)    // 24 histogram rows per slice (with halo)
#define HP     132             // hist y pitch (y in 0..128; 129..131 zero), mult of 4
#define M1P    140             // m1 pitch, mult of 4 (cols 0..135 read; 136..139 pad)
#define PTS_F  (NP*2)
#define HS_F   (LR*HP)         // 3168
#define M1_F   (SR*M1P)        // 2240
#define SMEM_F (HS_F + M1_F + PTS_F)   // 5440 floats = 21.76 KB -> 8 CTAs/SM

// Branchless tanh(x) for x>=0; for x<=0.01, tanh(x)=x within 3.3e-7 abs.
// A warp nearly always has >=1 lane on the exp path, so the branch never
// saved MUFU at warp level — selection avoids BSSY/BSYNC entirely.
__device__ __forceinline__ float tanh_pos(float x) {
    float e = __expf(x + x);                      // inf-safe: e=inf -> r=1
    float r = 1.0f - __fdividef(2.0f, e + 1.0f);
    return (x > 0.01f) ? r : x;                   // FSEL
}

__global__ __launch_bounds__(BT, 8)
void plotline2_kernel(const float* __restrict__ points, float* __restrict__ out)
{
    extern __shared__ float sm[];
    float* hs  = sm;                 // [LR][HP]
    float* m1  = sm + HS_F;          // [SR][M1P]; col c = conv-x at hist-y = c-4
    float* pts = sm + HS_F + M1_F;   // [NP*2]

    const int n   = blockIdx.x >> 3;
    const int q   = blockIdx.x & 7;
    const int s0  = q * SR;
    const int tid = threadIdx.x;

    // Compile-time taps exp(-d^2) -> FFMA immediates
    constexpr float W[KW] = {
        1.1253517471925912e-7f, 1.2340980408667956e-4f, 0.018315638888734179f,
        0.36787944117144233f, 1.0f, 0.36787944117144233f,
        0.018315638888734179f, 1.2340980408667956e-4f, 1.1253517471925912e-7f
    };

    // ---- zero hs (full) + m1 halo cols (0..3, 132..135) + preload points ----
    {
        float4 z = make_float4(0.f, 0.f, 0.f, 0.f);
        float4* h4 = (float4*)hs;
        for (int i = tid; i < HS_F / 4; i += BT) h4[i] = z;
        if (tid < SR) {
            *(float4*)&m1[tid * M1P]       = z;   // cols 0..3
            *(float4*)&m1[tid * M1P + 132] = z;   // cols 132..135 (132 rewritten)
        }
        if (tid < PTS_F) pts[tid] = points[n * PTS_F + tid];
    }
    __syncthreads();

    // ---- stage 1: interpolate, histogram points in our x-window ----
    // Seg-major mapping: lanes 0..15 of a warp share one segment (bi = step
    // base), lanes 16..31 the next. Per segment, solve the conservative
    // t-interval where rint(x) can land in [lrbase, lrbase+LR) and loop only
    // over in-range steps. Body keeps the exact guard, so culling only needs
    // to never skip a valid step (interval widened by 1 step both ways).
    const float inv = 1.0f / (float)SDIM;
    const int lrbase = s0 - RAD;
    if (tid < 240) {
        int seg = tid >> 4;                // 0..14
        int bi  = tid & 15;                // 0..15; steps i = bi + 16j
        float x0 = pts[seg * 2 + 0];
        float y0 = pts[seg * 2 + 1];
        float x1 = pts[seg * 2 + 2];
        float y1 = pts[seg * 2 + 3];

        float lo = (float)lrbase - 0.501f;          // x > lrbase-0.5 (inclusive-safe)
        float hi = (float)(lrbase + LR - 1) + 0.501f;
        float dx = x1 - x0;
        int iA, iB;
        if (dx != 0.0f) {
            float ta = __fdividef(lo - x0, dx);
            float tb = __fdividef(hi - x0, dx);
            float tmin = fmaxf(fminf(ta, tb), 0.0f);
            float tmax = fminf(fmaxf(ta, tb), 1.0f);
            iA = (int)floorf(tmin * 128.0f) - 1;    // widen 1 step (covers div err)
            iB = (int)ceilf (tmax * 128.0f) + 1;
        } else {
            bool in = (x0 > lo) && (x0 < hi);
            iA = in ? 0 : 1;
            iB = in ? 127 : 0;                      // empty interval when out
        }
        if (iA < 0) iA = 0;
        if (iB > 127) iB = 127;
        int jlo = (iA - bi + 15) >> 4;              // ceil((iA-bi)/16)
        if (jlo < 0) jlo = 0;
        int jhi = (iB - bi) >> 4;                   // floor
        if (jhi > 7) jhi = 7;

        for (int j = jlo; j <= jhi; ++j) {
            float fi  = (float)(bi + (j << 4));
            float t   = __fmul_rn(fi, inv);         // exact i/128
            float omt = 1.0f - t;
            // match XLA: mul, mul, add — no fma contraction
            float x = __fadd_rn(__fmul_rn(omt, x0), __fmul_rn(t, x1));
            int ix = (int)rintf(x);                 // round-half-to-even
            int lr = ix - lrbase;
            if ((unsigned)lr < (unsigned)LR) {
                float y = __fadd_rn(__fmul_rn(omt, y0), __fmul_rn(t, y1));
                int iy = (int)rintf(y);
                atomicAdd(&hs[lr * HP + iy], 1.0f);
            }
        }
    }
    __syncthreads();

    // ---- stage 2: conv over x: m1[s][y+4] = sum_d W[d]*hs[s+d][y] ----
    // 4-row groups; lanes -> consecutive y (stride 1, conflict-free).
    for (int item = tid; item < 4 * 129; item += BT) {
        int g = item / 129;                // row group 0..3
        int y = item - g * 129;            // 0..128
        int sb = g * 4;
        float v[4 + KW - 1];               // 12
#pragma unroll
        for (int j = 0; j < 4 + KW - 1; ++j)
            v[j] = hs[(sb + j) * HP + y];
#pragma unroll
        for (int i = 0; i < 4; ++i) {
            float acc = 0.0f;
#pragma unroll
            for (int d = 0; d < KW; ++d)
                acc = fmaf(W[d], v[i + d], acc);
            m1[(sb + i) * M1P + (y + RAD)] = acc;
        }
    }
    __syncthreads();

    // ---- stage 3: conv over t + tanh -> DIRECT coalesced gmem store ----
    // Warp w: rows s=w and s=w+8. Lane l -> t = 4l..4l+3: three aligned
    // LDS.128 per row (conflict-free), one STG.128 per row (full 512B row).
    {
        const int w = tid >> 5;
        const int l = tid & 31;
        float* outn = out + ((size_t)n * SDIM + s0) * SDIM;
#pragma unroll
        for (int rr = 0; rr < 2; ++rr) {
            int s = w + rr * 8;
            const float* row = m1 + s * M1P + 4 * l;
            float4 a = *(const float4*)(row);
            float4 b = *(const float4*)(row + 4);
            float4 c = *(const float4*)(row + 8);
            float v[12] = { a.x, a.y, a.z, a.w, b.x, b.y, b.z, b.w,
                            c.x, c.y, c.z, c.w };
            float r[4];
#pragma unroll
            for (int i = 0; i < 4; ++i) {
                float acc = 0.0f;
#pragma unroll
                for (int d = 0; d < KW; ++d)
                    acc = fmaf(W[d], v[i + d], acc);
                r[i] = tanh_pos(acc);
            }
            *(float4*)(outn + s * SDIM + 4 * l) = make_float4(r[0], r[1], r[2], r[3]);
        }
    }
}

extern "C" void kernel_launch(void* const* d_in, const int* in_sizes, int n_in,
                              void* d_out, int out_size)
{
    const float* points = (const float*)d_in[0];
    float* out = (float*)d_out;

    size_t smem = SMEM_F * sizeof(float);   // ~21.8 KB
    cudaFuncSetAttribute(plotline2_kernel,
                         cudaFuncAttributeMaxDynamicSharedMemorySize, (int)smem);
    plotline2_kernel<<<NIMG * SLICES, BT, smem>>>(points, out);
}